// round 6
// baseline (speedup 1.0000x reference)
#include <cuda_runtime.h>

#define MQ 32
#define NG 256
#define DD 128

__device__ __forceinline__ unsigned long long pack2(float lo, float hi) {
    unsigned long long r;
    asm("mov.b64 %0, {%1, %2};" : "=l"(r) : "f"(lo), "f"(hi));
    return r;
}
__device__ __forceinline__ unsigned long long fma2(unsigned long long a,
                                                   unsigned long long b,
                                                   unsigned long long c) {
    unsigned long long d;
    asm("fma.rn.f32x2 %0, %1, %2, %3;" : "=l"(d) : "l"(a), "l"(b), "l"(c));
    return d;
}
__device__ __forceinline__ unsigned long long add2(unsigned long long a,
                                                   unsigned long long b) {
    unsigned long long d;
    asm("add.rn.f32x2 %0, %1, %2;" : "=l"(d) : "l"(a), "l"(b));
    return d;
}
__device__ __forceinline__ unsigned long long abs2(unsigned long long a) {
    unsigned long long d;
    asm("and.b64 %0, %1, 0x7FFFFFFF7FFFFFFF;" : "=l"(d) : "l"(a));  // 2x LOP3, alu pipe
    return d;
}
__device__ __forceinline__ void unpack2(unsigned long long v, float& lo, float& hi) {
    asm("mov.b64 {%0, %1}, %2;" : "=f"(lo), "=f"(hi) : "l"(v));
}

// Block = one gallery item j. 512 threads; thread owns a-rows (t>>4)*4..+3 and
// b-cols {4m..4m+3, 64+4m..64+4m+3} (m = t&15): conflict-free LDS.128.
// pen(i,j) = 16384*ze + 0.5*( su_i^2 - sumMp - 16384*ze + sum|t'| ),
// t' = ua*ub - Mp - ze.  Inner math fully packed: FFMA2 (fma pipe) +
// AND64 abs (alu pipe) + FADD2 accumulate (fma pipe) -> pipes balanced.
__global__ __launch_bounds__(512, 2)
void jacc_pen_kernel(const float* __restrict__ qf,
                     const float* __restrict__ x,
                     const float* __restrict__ Mp,
                     const float* __restrict__ zep,
                     float* __restrict__ out) {
    const int j = blockIdx.x;
    const int t = threadIdx.x;
    const float ze = *zep;

    __shared__ __align__(16) float u_s[MQ][DD];   // 16 KB
    __shared__ float part_s[MQ][128];             // 16 KB
    __shared__ float su_s[MQ], sv_s[MQ];
    __shared__ float sMw_s[16];

    const float* __restrict__ xj = x + j * DD;

    // ---- u[i][d] = max(qf[i][d], x[j][d]) ----
    #pragma unroll
    for (int k = 0; k < (MQ * DD) / 512; ++k) {
        int e = t + 512 * k;
        int i = e >> 7;
        int d = e & (DD - 1);
        u_s[i][d] = fmaxf(qf[e], xj[d]);
    }

    // ---- dist0 row sums: i = t/16, 16 lanes per i ----
    {
        int i  = t >> 4;
        int d0 = (t & 15) * 8;
        float su = 0.0f, sv = 0.0f;
        #pragma unroll
        for (int d = 0; d < 8; ++d) {
            float q  = qf[i * DD + d0 + d];
            float xv = xj[d0 + d];
            su += fmaxf(q, xv);
            sv += fminf(q, xv);
        }
        #pragma unroll
        for (int off = 8; off >= 1; off >>= 1) {
            su += __shfl_down_sync(0xffffffffu, su, off, 16);
            sv += __shfl_down_sync(0xffffffffu, sv, off, 16);
        }
        if ((t & 15) == 0) { su_s[i] = su; sv_s[i] = sv; }
    }

    // ---- Load 4x8 Mp tile, pack (-Mp - ze) as f32x2 ----
    const int a0 = (t >> 4) * 4;
    const int m  = t & 15;
    const int bA = 4 * m;
    const int bB = 64 + 4 * m;
    unsigned long long nM2[4][4];
    {
        float msum = 0.0f;
        #pragma unroll
        for (int aa = 0; aa < 4; ++aa) {
            float4 m0 = *reinterpret_cast<const float4*>(Mp + (a0 + aa) * DD + bA);
            float4 m1 = *reinterpret_cast<const float4*>(Mp + (a0 + aa) * DD + bB);
            msum += ((m0.x + m0.y) + (m0.z + m0.w)) + ((m1.x + m1.y) + (m1.z + m1.w));
            nM2[aa][0] = pack2(-m0.x - ze, -m0.y - ze);
            nM2[aa][1] = pack2(-m0.z - ze, -m0.w - ze);
            nM2[aa][2] = pack2(-m1.x - ze, -m1.y - ze);
            nM2[aa][3] = pack2(-m1.z - ze, -m1.w - ze);
        }
        #pragma unroll
        for (int off = 16; off >= 1; off >>= 1)
            msum += __shfl_xor_sync(0xffffffffu, msum, off);
        if ((t & 31) == 0) sMw_s[t >> 5] = msum;
    }

    __syncthreads();

    // ---- Hot loop ----
    const float* ua_p = &u_s[0][a0];
    const float* ub_p = &u_s[0][bA];
    float* st_p = &part_s[0][t >> 2];
    #pragma unroll 1
    for (int i = 0; i < MQ; ++i) {
        float4 va = *reinterpret_cast<const float4*>(ua_p);
        ulonglong2 c0 = *reinterpret_cast<const ulonglong2*>(ub_p);
        ulonglong2 c1 = *reinterpret_cast<const ulonglong2*>(ub_p + 64);
        unsigned long long ub2[4] = {c0.x, c0.y, c1.x, c1.y};
        float ua[4] = {va.x, va.y, va.z, va.w};

        unsigned long long acc0 = 0ULL, acc1 = 0ULL;
        #pragma unroll
        for (int aa = 0; aa < 4; ++aa) {
            unsigned long long ua2 = pack2(ua[aa], ua[aa]);
            #pragma unroll
            for (int bpp = 0; bpp < 4; ++bpp) {
                unsigned long long t2 = fma2(ua2, ub2[bpp], nM2[aa][bpp]);
                unsigned long long a2v = abs2(t2);          // alu pipe
                if (bpp & 1) acc1 = add2(acc1, a2v);        // fma pipe, packed
                else         acc0 = add2(acc0, a2v);
            }
        }
        float lo, hi;
        unpack2(add2(acc0, acc1), lo, hi);
        float w = lo + hi;

        // quad reduce (2 shfl), predicated STS
        w += __shfl_down_sync(0xffffffffu, w, 2, 4);
        w += __shfl_down_sync(0xffffffffu, w, 1, 4);
        if ((t & 3) == 0) *st_p = w;

        ua_p += DD;
        ub_p += DD;
        st_p += 128;
    }

    __syncthreads();

    // ---- Final phase: 16 warps x 2 queries each ----
    {
        const int w = t >> 5;
        const int l = t & 31;

        float sm = 0.0f;
        #pragma unroll
        for (int k = 0; k < 16; ++k) sm += sMw_s[k];

        #pragma unroll
        for (int ii = 0; ii < 2; ++ii) {
            int i = w * 2 + ii;
            float p = (part_s[i][l]      + part_s[i][l + 32])
                    + (part_s[i][l + 64] + part_s[i][l + 96]);
            #pragma unroll
            for (int off = 16; off >= 1; off >>= 1)
                p += __shfl_xor_sync(0xffffffffu, p, off);
            if (l == 0) {
                float su = su_s[i];
                const float NE = (float)(DD * DD);  // 16384
                float pen = NE * ze + 0.5f * ((su * su - sm - NE * ze) + p);
                out[i * NG + j] = sv_s[i] / su - 0.001f * pen;
            }
        }
    }
}

extern "C" void kernel_launch(void* const* d_in, const int* in_sizes, int n_in,
                              void* d_out, int out_size) {
    const float* qf = (const float*)d_in[0];   // (32, 128)
    const float* x  = (const float*)d_in[1];   // (256, 128)
    const float* Mp = (const float*)d_in[2];   // (128, 128)
    const float* ze = (const float*)d_in[3];   // scalar
    float* out = (float*)d_out;                // (32, 256)
    (void)in_sizes; (void)n_in; (void)out_size;

    jacc_pen_kernel<<<NG, 512>>>(qf, x, Mp, ze, out);
}

// round 7
// speedup vs baseline: 1.1755x; 1.1755x over previous
#include <cuda_runtime.h>

#define MQ 32
#define NG 256
#define DD 128

__device__ __forceinline__ unsigned long long pack2(float lo, float hi) {
    unsigned long long r;
    asm("mov.b64 %0, {%1, %2};" : "=l"(r) : "f"(lo), "f"(hi));
    return r;
}
__device__ __forceinline__ unsigned long long fma2(unsigned long long a,
                                                   unsigned long long b,
                                                   unsigned long long c) {
    unsigned long long d;
    asm("fma.rn.f32x2 %0, %1, %2, %3;" : "=l"(d) : "l"(a), "l"(b), "l"(c));
    return d;
}
__device__ __forceinline__ void unpack2(unsigned long long v, float& lo, float& hi) {
    asm("mov.b64 {%0, %1}, %2;" : "=f"(lo), "=f"(hi) : "l"(v));
}

// Block = one gallery item j. 512 threads; thread owns a-rows (t>>4)*4..+3 and
// b-cols {4m..4m+3, 64+4m..64+4m+3} (m = t&15): conflict-free LDS.128.
// pen(i,j) = 16384*ze + 0.5*( su_i^2 - sumMp - 16384*ze + sum|t'| ),
// t' = ua*ub - Mp - ze.  Inner: FFMA2 + FADD-with-|src| (R5 form).
// 4 queries per outer pass; their quad-reductions run as 4 parallel shfl
// chains so the dependent tail is amortized 4x.
__global__ __launch_bounds__(512, 2)
void jacc_pen_kernel(const float* __restrict__ qf,
                     const float* __restrict__ x,
                     const float* __restrict__ Mp,
                     const float* __restrict__ zep,
                     float* __restrict__ out) {
    const int j = blockIdx.x;
    const int t = threadIdx.x;
    const float ze = *zep;

    __shared__ __align__(16) float u_s[MQ][DD];   // 16 KB
    __shared__ float part_s[MQ][128];             // 16 KB
    __shared__ float su_s[MQ], sv_s[MQ];
    __shared__ float sMw_s[16];

    const float* __restrict__ xj = x + j * DD;

    // ---- u[i][d] = max(qf[i][d], x[j][d]) ----
    #pragma unroll
    for (int k = 0; k < (MQ * DD) / 512; ++k) {
        int e = t + 512 * k;
        int i = e >> 7;
        int d = e & (DD - 1);
        u_s[i][d] = fmaxf(qf[e], xj[d]);
    }

    // ---- dist0 row sums: i = t/16, 16 lanes per i ----
    {
        int i  = t >> 4;
        int d0 = (t & 15) * 8;
        float su = 0.0f, sv = 0.0f;
        #pragma unroll
        for (int d = 0; d < 8; ++d) {
            float q  = qf[i * DD + d0 + d];
            float xv = xj[d0 + d];
            su += fmaxf(q, xv);
            sv += fminf(q, xv);
        }
        #pragma unroll
        for (int off = 8; off >= 1; off >>= 1) {
            su += __shfl_down_sync(0xffffffffu, su, off, 16);
            sv += __shfl_down_sync(0xffffffffu, sv, off, 16);
        }
        if ((t & 15) == 0) { su_s[i] = su; sv_s[i] = sv; }
    }

    // ---- Load 4x8 Mp tile, pack (-Mp - ze) as f32x2 ----
    const int a0 = (t >> 4) * 4;
    const int m  = t & 15;
    const int bA = 4 * m;
    const int bB = 64 + 4 * m;
    unsigned long long nM2[4][4];
    {
        float msum = 0.0f;
        #pragma unroll
        for (int aa = 0; aa < 4; ++aa) {
            float4 m0 = *reinterpret_cast<const float4*>(Mp + (a0 + aa) * DD + bA);
            float4 m1 = *reinterpret_cast<const float4*>(Mp + (a0 + aa) * DD + bB);
            msum += ((m0.x + m0.y) + (m0.z + m0.w)) + ((m1.x + m1.y) + (m1.z + m1.w));
            nM2[aa][0] = pack2(-m0.x - ze, -m0.y - ze);
            nM2[aa][1] = pack2(-m0.z - ze, -m0.w - ze);
            nM2[aa][2] = pack2(-m1.x - ze, -m1.y - ze);
            nM2[aa][3] = pack2(-m1.z - ze, -m1.w - ze);
        }
        #pragma unroll
        for (int off = 16; off >= 1; off >>= 1)
            msum += __shfl_xor_sync(0xffffffffu, msum, off);
        if ((t & 31) == 0) sMw_s[t >> 5] = msum;
    }

    __syncthreads();

    // ---- Hot loop: 4 queries per pass; deferred parallel reductions ----
    const float* ua_p = &u_s[0][a0];
    const float* ub_p = &u_s[0][bA];
    float* st_p = &part_s[0][t >> 2];
    #pragma unroll 1
    for (int ig = 0; ig < MQ; ig += 4) {
        float w[4];
        #pragma unroll
        for (int s = 0; s < 4; ++s) {
            const float* uap = ua_p + s * DD;
            const float* ubp = ub_p + s * DD;
            float4 va = *reinterpret_cast<const float4*>(uap);
            ulonglong2 c0 = *reinterpret_cast<const ulonglong2*>(ubp);
            ulonglong2 c1 = *reinterpret_cast<const ulonglong2*>(ubp + 64);
            unsigned long long ub2[4] = {c0.x, c0.y, c1.x, c1.y};
            float ua[4] = {va.x, va.y, va.z, va.w};

            float acc[4] = {0.0f, 0.0f, 0.0f, 0.0f};
            #pragma unroll
            for (int aa = 0; aa < 4; ++aa) {
                unsigned long long ua2 = pack2(ua[aa], ua[aa]);
                #pragma unroll
                for (int bpp = 0; bpp < 4; ++bpp) {
                    float lo, hi;
                    unpack2(fma2(ua2, ub2[bpp], nM2[aa][bpp]), lo, hi);
                    acc[bpp] += fabsf(lo);              // FADD with |src| modifier
                    acc[(bpp + 2) & 3] += fabsf(hi);
                }
            }
            w[s] = (acc[0] + acc[1]) + (acc[2] + acc[3]);
        }

        // 4 independent quad reductions: shfl chains overlap
        #pragma unroll
        for (int s = 0; s < 4; ++s)
            w[s] += __shfl_down_sync(0xffffffffu, w[s], 2, 4);
        #pragma unroll
        for (int s = 0; s < 4; ++s)
            w[s] += __shfl_down_sync(0xffffffffu, w[s], 1, 4);
        if ((t & 3) == 0) {
            #pragma unroll
            for (int s = 0; s < 4; ++s)
                st_p[s * 128] = w[s];
        }

        ua_p += 4 * DD;
        ub_p += 4 * DD;
        st_p += 4 * 128;
    }

    __syncthreads();

    // ---- Final phase: 16 warps x 2 queries each ----
    {
        const int w = t >> 5;
        const int l = t & 31;

        float sm = 0.0f;
        #pragma unroll
        for (int k = 0; k < 16; ++k) sm += sMw_s[k];

        #pragma unroll
        for (int ii = 0; ii < 2; ++ii) {
            int i = w * 2 + ii;
            float p = (part_s[i][l]      + part_s[i][l + 32])
                    + (part_s[i][l + 64] + part_s[i][l + 96]);
            #pragma unroll
            for (int off = 16; off >= 1; off >>= 1)
                p += __shfl_xor_sync(0xffffffffu, p, off);
            if (l == 0) {
                float su = su_s[i];
                const float NE = (float)(DD * DD);  // 16384
                float pen = NE * ze + 0.5f * ((su * su - sm - NE * ze) + p);
                out[i * NG + j] = sv_s[i] / su - 0.001f * pen;
            }
        }
    }
}

extern "C" void kernel_launch(void* const* d_in, const int* in_sizes, int n_in,
                              void* d_out, int out_size) {
    const float* qf = (const float*)d_in[0];   // (32, 128)
    const float* x  = (const float*)d_in[1];   // (256, 128)
    const float* Mp = (const float*)d_in[2];   // (128, 128)
    const float* ze = (const float*)d_in[3];   // scalar
    float* out = (float*)d_out;                // (32, 256)
    (void)in_sizes; (void)n_in; (void)out_size;

    jacc_pen_kernel<<<NG, 512>>>(qf, x, Mp, ze, out);
}